// round 14
// baseline (speedup 1.0000x reference)
#include <cuda_runtime.h>
#include <cuda_bf16.h>
#include <cuda_fp16.h>
#include <stdint.h>

#define NB 96
#define NQ 96
#define NV 197
#define NT 77
#define ND 768
#define NE 512
#define RV (NB*NV)
#define RT (NQ*NT)

// scratch (static device globals — no allocation allowed)
__device__ float g_Pv[RV*NE];
__device__ float g_Pt[RT*NE];
__device__ __half g_vtok[RV*NE];
__device__ __half g_ttok[RT*NE];
__device__ float g_cm[2][NB*NQ*80];   // per-half column maxima
__device__ float g_rs[2][NB*NQ];      // per-half row-max partial sums
// fp16 copies of token-GEMM inputs
__device__ __half g_Xvb[RV*ND];
__device__ __half g_Xtb[RT*ND];
__device__ __half g_Wvb[NE*ND];
__device__ __half g_Wtb[NE*ND];

__device__ __forceinline__ uint32_t smem_u32(const void* p){
    return (uint32_t)__cvta_generic_to_shared(p);
}
__device__ __forceinline__ void cp16(uint32_t dst, const void* src, int sz){
    asm volatile("cp.async.cg.shared.global [%0], [%1], 16, %2;\n"
                 :: "r"(dst), "l"(src), "r"(sz));
}
__device__ __forceinline__ void cp_commit(){ asm volatile("cp.async.commit_group;\n"); }
template<int N> __device__ __forceinline__ void cp_wait(){
    asm volatile("cp.async.wait_group %0;\n" :: "n"(N));
}
// fp16 x fp16 -> fp16 accum mma (halves acc register footprint)
__device__ __forceinline__ void mma_f16(uint32_t c[2], const uint32_t a[4], const uint32_t b[2]){
    asm volatile(
      "mma.sync.aligned.m16n8k16.row.col.f16.f16.f16.f16 "
      "{%0,%1},{%2,%3,%4,%5},{%6,%7},{%0,%1};\n"
      : "+r"(c[0]), "+r"(c[1])
      : "r"(a[0]),"r"(a[1]),"r"(a[2]),"r"(a[3]),"r"(b[0]),"r"(b[1]));
}
__device__ __forceinline__ float2 h2f(uint32_t u){
    __half2 h = *reinterpret_cast<__half2*>(&u);
    return __half22float2(h);
}
__device__ __forceinline__ void ldsm_x4(uint32_t r[4], uint32_t addr){
    asm volatile("ldmatrix.sync.aligned.m8n8.x4.shared.b16 {%0,%1,%2,%3}, [%4];"
                 : "=r"(r[0]), "=r"(r[1]), "=r"(r[2]), "=r"(r[3]) : "r"(addr));
}
__device__ __forceinline__ void ldsm_x2(uint32_t r[2], uint32_t addr){
    asm volatile("ldmatrix.sync.aligned.m8n8.x2.shared.b16 {%0,%1}, [%2];"
                 : "=r"(r[0]), "=r"(r[1]) : "r"(addr));
}

// ---------------------------------------------------------------------------
// K0: fp32 -> fp16 conversion for token GEMM inputs
// ---------------------------------------------------------------------------
__global__ __launch_bounds__(256) void cvt_kernel(
    const float* __restrict__ Xv, const float* __restrict__ Xt,
    const float* __restrict__ Wv, const float* __restrict__ Wt)
{
    const int NQ4 = ND/4;
    const int total = (RV + RT + 2*NE) * NQ4;
    int i = blockIdx.x*blockDim.x + threadIdx.x;
    if (i >= total) return;
    const float* src; __half* dst; int off = i;
    if (off < RV*NQ4){ src = Xv; dst = g_Xvb; }
    else if ((off -= RV*NQ4) < RT*NQ4){ src = Xt; dst = g_Xtb; }
    else if ((off -= RT*NQ4) < NE*NQ4){ src = Wv; dst = g_Wvb; }
    else { off -= NE*NQ4; src = Wt; dst = g_Wtb; }
    float4 v = ((const float4*)src)[off];
    __half2 lo = __floats2half2_rn(v.x, v.y);
    __half2 hi = __floats2half2_rn(v.z, v.w);
    uint2 u; u.x = *(uint32_t*)&lo; u.y = *(uint32_t*)&hi;
    ((uint2*)dst)[off] = u;
}

// ---------------------------------------------------------------------------
// K1: cls projections (pure FP32, accuracy-critical outputs)
// ---------------------------------------------------------------------------
__global__ __launch_bounds__(256) void cls_gemm(
    const float* __restrict__ Xv, const float* __restrict__ Xt,
    const float* __restrict__ Wv, const float* __restrict__ bv,
    const float* __restrict__ Wt, const float* __restrict__ bt,
    float* __restrict__ out)
{
    __shared__ float Xs[16][64];
    __shared__ float Ws[64][65];
    const int which = blockIdx.z;
    const float* X    = which ? Xt : Xv;
    const float* W    = which ? Wt : Wv;
    const float* bias = which ? bt : bv;
    const int m0 = blockIdx.x * 16;
    const int n0 = blockIdx.y * 64;
    const int tid = threadIdx.x;
    float acc[4] = {0.f,0.f,0.f,0.f};
    const int jj = tid & 63;
    const int r4 = (tid >> 6) * 4;

    for (int k0 = 0; k0 < ND; k0 += 64){
        {
            int r = tid >> 4, kv = tid & 15;
            float4 x4 = *(const float4*)(X + (size_t)(m0 + r)*ND + k0 + kv*4);
            Xs[r][kv*4+0]=x4.x; Xs[r][kv*4+1]=x4.y; Xs[r][kv*4+2]=x4.z; Xs[r][kv*4+3]=x4.w;
        }
        #pragma unroll
        for (int i = 0; i < 4; i++){
            int seg = tid + 256*i; int r = seg >> 4, kv = seg & 15;
            float4 w4 = *(const float4*)(W + (size_t)(n0 + r)*ND + k0 + kv*4);
            Ws[r][kv*4+0]=w4.x; Ws[r][kv*4+1]=w4.y; Ws[r][kv*4+2]=w4.z; Ws[r][kv*4+3]=w4.w;
        }
        __syncthreads();
        #pragma unroll
        for (int k = 0; k < 64; k++){
            float w = Ws[jj][k];
            acc[0] += Xs[r4+0][k]*w;
            acc[1] += Xs[r4+1][k]*w;
            acc[2] += Xs[r4+2][k]*w;
            acc[3] += Xs[r4+3][k]*w;
        }
        __syncthreads();
    }
    float bb = bias[n0 + jj];
    float* o = out + (size_t)which*(NB*NE);
    #pragma unroll
    for (int i = 0; i < 4; i++)
        o[(size_t)(m0 + r4 + i)*NE + n0 + jj] = acc[i] + bb;
}

// ---------------------------------------------------------------------------
// K2: merged token projection GEMM (fp16 m16n8k16, fp16 accum, 3 CTAs/SM).
// grid.x in [0,148): visual rows; [148,206): textual rows. grid.y: n-tiles.
// ---------------------------------------------------------------------------
#define ASTRIDE 144          // 72 fp16 per row (64 data + 8 pad)
#define TOK_SMEM 73728       // A[2][128][72] + B[2][128][72] fp16
#define TOK_VBLK 148         // ceil(RV/128)

__global__ __launch_bounds__(256,3) void tok_gemm4(
    const float* __restrict__ bv, const float* __restrict__ bt)
{
    extern __shared__ char smem[];
    const uint32_t aB = smem_u32(smem);
    const uint32_t bB = aB + 36864;
    const int which = (blockIdx.x >= TOK_VBLK) ? 1 : 0;
    const int bx = which ? (blockIdx.x - TOK_VBLK) : blockIdx.x;
    const int R = which ? RT : RV;
    const float* bias = which ? bt : bv;
    const __half* X = which ? g_Xtb : g_Xvb;
    const __half* W = which ? g_Wtb : g_Wvb;
    float* P = which ? g_Pt : g_Pv;
    const int m0 = bx*128, n0 = blockIdx.y*128;
    const int tid = threadIdx.x, lane = tid & 31, warp = tid >> 5;
    const int wm = warp >> 1, wn = warp & 1;
    uint32_t acc[2][8][2] = {};

    const uint32_t a_lane = aB + (uint32_t)(wm*32 + (lane & 15))*ASTRIDE
                               + (uint32_t)((lane >> 4) & 1)*16;
    const uint32_t b_lane = bB + (uint32_t)(wn*64 + (lane & 7) + ((lane >> 4) & 1)*8)*ASTRIDE
                               + (uint32_t)((lane >> 3) & 1)*16;

    auto loadc = [&](int buf, int kc){
        const int k0 = kc*64;
        #pragma unroll
        for (int i = 0; i < 4; i++){
            int seg = tid + 256*i; int r = seg >> 3, kv = seg & 7;
            uint32_t dst = aB + (uint32_t)buf*18432 + (uint32_t)r*ASTRIDE + (uint32_t)kv*16;
            int gr = m0 + r;
            const __half* src = X + (size_t)(gr < R ? gr : 0)*ND + k0 + kv*8;
            cp16(dst, src, gr < R ? 16 : 0);
        }
        #pragma unroll
        for (int i = 0; i < 4; i++){
            int seg = tid + 256*i; int r = seg >> 3, kv = seg & 7;
            uint32_t dst = bB + (uint32_t)buf*18432 + (uint32_t)r*ASTRIDE + (uint32_t)kv*16;
            const __half* src = W + (size_t)(n0 + r)*ND + k0 + kv*8;
            cp16(dst, src, 16);
        }
    };

    loadc(0, 0); cp_commit();
    for (int kc = 0; kc < 12; kc++){
        cp_wait<0>();
        __syncthreads();                       // single sync: RAW + WAR
        if (kc < 11){ loadc((kc+1)&1, kc+1); cp_commit(); }
        const uint32_t abuf = a_lane + (uint32_t)(kc & 1)*18432;
        const uint32_t bbuf = b_lane + (uint32_t)(kc & 1)*18432;
        #pragma unroll
        for (int ks = 0; ks < 4; ks++){
            const uint32_t ko = (uint32_t)ks*32;
            uint32_t a[2][4], bfr[16];
            ldsm_x4(a[0], abuf + ko);
            ldsm_x4(a[1], abuf + 16*ASTRIDE + ko);
            ldsm_x4(&bfr[0],  bbuf + ko);
            ldsm_x4(&bfr[4],  bbuf + 16*ASTRIDE + ko);
            ldsm_x4(&bfr[8],  bbuf + 32*ASTRIDE + ko);
            ldsm_x4(&bfr[12], bbuf + 48*ASTRIDE + ko);
            #pragma unroll
            for (int mt = 0; mt < 2; mt++)
                #pragma unroll
                for (int nt = 0; nt < 8; nt++)
                    mma_f16(acc[mt][nt], a[mt], &bfr[nt*2]);
        }
    }

    #pragma unroll
    for (int mt = 0; mt < 2; mt++){
        #pragma unroll
        for (int nt = 0; nt < 8; nt++){
            int r = m0 + wm*32 + mt*16 + (lane >> 2);
            int c = n0 + wn*64 + nt*8 + (lane & 3)*2;
            float b0 = bias[c], b1 = bias[c+1];
            float2 lo = h2f(acc[mt][nt][0]);
            float2 hi = h2f(acc[mt][nt][1]);
            if (r < R){
                P[(size_t)r*NE + c  ] = lo.x + b0;
                P[(size_t)r*NE + c+1] = lo.y + b1;
            }
            if (r + 8 < R){
                P[(size_t)(r+8)*NE + c  ] = hi.x + b0;
                P[(size_t)(r+8)*NE + c+1] = hi.y + b1;
            }
        }
    }
}

// ---------------------------------------------------------------------------
// K3: merged l2-normalize (visual + textual rows) -> fp16 tokens
// ---------------------------------------------------------------------------
__global__ __launch_bounds__(256) void norm_kernel3()
{
    int row  = blockIdx.x*8 + (threadIdx.x >> 5);
    const int lane = threadIdx.x & 31;
    const float* P; __half* O;
    if (row < RV){ P = g_Pv; O = g_vtok; }
    else { row -= RV; if (row >= RT) return; P = g_Pt; O = g_ttok; }
    const float4* p = (const float4*)(P + (size_t)row*NE);
    float4 v[4]; float ss = 0.f;
    #pragma unroll
    for (int i = 0; i < 4; i++){
        v[i] = p[lane + 32*i];
        ss += v[i].x*v[i].x + v[i].y*v[i].y + v[i].z*v[i].z + v[i].w*v[i].w;
    }
    #pragma unroll
    for (int o = 16; o > 0; o >>= 1) ss += __shfl_xor_sync(0xffffffffu, ss, o);
    const float s = 1.f / fmaxf(sqrtf(ss), 1e-12f);
    uint2* ob = (uint2*)(O + (size_t)row*NE);
    #pragma unroll
    for (int i = 0; i < 4; i++){
        __half2 lo = __floats2half2_rn(v[i].x*s, v[i].y*s);
        __half2 hi = __floats2half2_rn(v[i].z*s, v[i].w*s);
        uint2 u; u.x = *(uint32_t*)&lo; u.y = *(uint32_t*)&hi;
        ob[lane + 32*i] = u;
    }
}

// ---------------------------------------------------------------------------
// K4: fine-grained similarity. fp16 inputs + fp16 accum (acc 40 regs),
// K-chunk 32, 3-stage cp.async ring, 3 CTAs/SM. Templated on M-half Z.
// Grid (48, 96); CTA 256 thr, 8 warps (4x2), warp tile 32x40 per q, 2 q/CTA.
// ---------------------------------------------------------------------------
#define FGA 80               // bytes per row: 32 fp16 (64B) + 16B pad; bank-conflict-free
#define FG_ASTG 10240        // A stage: 128 rows x 80B
#define FG_BSTG 12800        // B stage: 2q x 80 rows x 80B
#define FG10_SMEM 69632      // 3*(10240+12800) = 69120, padded

template<int Z>
__global__ __launch_bounds__(256,3) void fg10_kernel(
    const int* __restrict__ text_length)
{
    extern __shared__ char smem[];
    const uint32_t aB = smem_u32(smem);
    const uint32_t bB = aB + 3*FG_ASTG;
    float* rowp = (float*)smem;            // [2q][2wn][128]  epilogue overlay
    float* colp = (float*)(smem + 4096);   // [2q][4wm][80]
    float* red  = (float*)(smem + 6656);   // [2q][8]

    const int q0 = blockIdx.x*2, b = blockIdx.y;
    constexpr int m_base = Z*128;
    constexpr int mrows  = Z ? 80 : 128;
    constexpr int vlim   = Z ? 69 : 128;
    const int tid = threadIdx.x, lane = tid & 31, warp = tid >> 5;
    const int wm = warp >> 1, wn = warp & 1;
    const int mtcnt = (Z == 0) ? 2 : (wm < 2 ? 2 : (wm == 2 ? 1 : 0));
    const __half* Ag  = g_vtok + (size_t)b*NV*NE;
    const __half* Bg0 = g_ttok + (size_t)q0*NT*NE;
    const __half* Bg1 = g_ttok + (size_t)(q0+1)*NT*NE;
    uint32_t acc[2][2][5][2] = {};   // [q][mt][nt][2]  fp16x2 pairs

    const uint32_t a_lane = aB + (uint32_t)(wm*32 + (lane & 15))*FGA
                               + (uint32_t)((lane >> 4) & 1)*16;
    const uint32_t b_pat  = (uint32_t)(wn*40 + (lane & 7) + ((lane >> 4) & 1)*8)*FGA
                               + (uint32_t)((lane >> 3) & 1)*16;

    auto loadc = [&](int st, int kc){
        const int k0 = kc*32;
        #pragma unroll
        for (int i = 0; i < 2; i++){           // A: mrows x 4 x 16B
            int seg = tid + 256*i;
            if (Z == 0 || seg < mrows*4){
                int r = seg >> 2, kv = seg & 3;
                uint32_t dst = aB + (uint32_t)st*FG_ASTG + (uint32_t)r*FGA + (uint32_t)kv*16;
                int gr = m_base + r;
                const __half* src = Ag + (size_t)(gr < NV ? gr : 0)*NE + k0 + kv*8;
                cp16(dst, src, gr < NV ? 16 : 0);
            }
        }
        #pragma unroll
        for (int i = 0; i < 3; i++){           // B: 2q x 80 x 4 = 640 segs
            int seg = tid + 256*i;
            if (seg < 640){
                int j  = seg / 320;
                int s2 = seg - j*320;
                int r = s2 >> 2, kv = s2 & 3;
                uint32_t dst = bB + (uint32_t)st*FG_BSTG + (uint32_t)j*6400
                             + (uint32_t)r*FGA + (uint32_t)kv*16;
                const __half* src = (j ? Bg1 : Bg0)
                                    + (size_t)(r < NT ? r : 0)*NE + k0 + kv*8;
                cp16(dst, src, r < NT ? 16 : 0);
            }
        }
    };

    loadc(0, 0); cp_commit();
    loadc(1, 1); cp_commit();
    for (int kc = 0; kc < 16; kc++){
        if (kc < 15) cp_wait<1>(); else cp_wait<0>();
        __syncthreads();                       // single sync: RAW + WAR
        if (kc < 14){ loadc((kc+2)%3, kc+2); cp_commit(); }
        const int st = kc % 3;
        const uint32_t abuf = a_lane + (uint32_t)st*FG_ASTG;
        const uint32_t b0   = bB + b_pat + (uint32_t)st*FG_BSTG;
        const uint32_t b1   = b0 + 6400;
        #pragma unroll
        for (int ks = 0; ks < 2; ks++){
            const uint32_t ko = (uint32_t)ks*32;
            uint32_t a[2][4], bf0[10], bf1[10];
            #pragma unroll
            for (int mt = 0; mt < 2; mt++)
                if (Z == 0 || mt < mtcnt) ldsm_x4(a[mt], abuf + (uint32_t)mt*(16*FGA) + ko);
            ldsm_x4(&bf0[0], b0 + ko);
            ldsm_x4(&bf0[4], b0 + 16*FGA + ko);
            ldsm_x2(&bf0[8], b0 + 32*FGA + ko);
            ldsm_x4(&bf1[0], b1 + ko);
            ldsm_x4(&bf1[4], b1 + 16*FGA + ko);
            ldsm_x2(&bf1[8], b1 + 32*FGA + ko);
            #pragma unroll
            for (int mt = 0; mt < 2; mt++)
                if (Z == 0 || mt < mtcnt){
                    #pragma unroll
                    for (int nt = 0; nt < 5; nt++){
                        mma_f16(acc[0][mt][nt], a[mt], &bf0[nt*2]);
                        mma_f16(acc[1][mt][nt], a[mt], &bf1[nt*2]);
                    }
                }
        }
    }
    __syncthreads();   // all warps done reading smem before epilogue overlays it

    // ---- epilogue: unpack fp16 accum, register-space masked reductions ----
    const int len0 = text_length[q0];
    const int len1 = text_length[q0+1];
    const float NEG = -3.0e38f;

    #pragma unroll
    for (int j = 0; j < 2; j++){
        const int len = j ? len1 : len0;
        #pragma unroll
        for (int mt = 0; mt < 2; mt++){
            if (Z == 0 || mt < mtcnt){
                float m0 = NEG, m1 = NEG;
                #pragma unroll
                for (int nt = 0; nt < 5; nt++){
                    int c0 = wn*40 + nt*8 + (lane & 3)*2;
                    float2 lo = h2f(acc[j][mt][nt][0]);
                    float2 hi = h2f(acc[j][mt][nt][1]);
                    if (c0 < len){ m0 = fmaxf(m0, lo.x); m1 = fmaxf(m1, hi.x); }
                    if (c0 + 1 < len){ m0 = fmaxf(m0, lo.y); m1 = fmaxf(m1, hi.y); }
                }
                m0 = fmaxf(m0, __shfl_xor_sync(0xffffffffu, m0, 1));
                m0 = fmaxf(m0, __shfl_xor_sync(0xffffffffu, m0, 2));
                m1 = fmaxf(m1, __shfl_xor_sync(0xffffffffu, m1, 1));
                m1 = fmaxf(m1, __shfl_xor_sync(0xffffffffu, m1, 2));
                if ((lane & 3) == 0){
                    int r = wm*32 + mt*16 + (lane >> 2);
                    rowp[j*256 + wn*128 + r]     = m0;
                    rowp[j*256 + wn*128 + r + 8] = m1;
                }
            } else if ((lane & 3) == 0){
                int r = wm*32 + mt*16 + (lane >> 2);
                rowp[j*256 + wn*128 + r]     = NEG;
                rowp[j*256 + wn*128 + r + 8] = NEG;
            }
        }
        #pragma unroll
        for (int nt = 0; nt < 5; nt++){
            float c0m = NEG, c1m = NEG;
            #pragma unroll
            for (int mt = 0; mt < 2; mt++){
                if (Z == 0 || mt < mtcnt){
                    int gr = m_base + wm*32 + mt*16 + (lane >> 2);
                    float2 lo = h2f(acc[j][mt][nt][0]);
                    float2 hi = h2f(acc[j][mt][nt][1]);
                    if (gr < NV){ c0m = fmaxf(c0m, lo.x); c1m = fmaxf(c1m, lo.y); }
                    if (gr + 8 < NV){ c0m = fmaxf(c0m, hi.x); c1m = fmaxf(c1m, hi.y); }
                }
            }
            #pragma unroll
            for (int o = 4; o <= 16; o <<= 1){
                c0m = fmaxf(c0m, __shfl_xor_sync(0xffffffffu, c0m, o));
                c1m = fmaxf(c1m, __shfl_xor_sync(0xffffffffu, c1m, o));
            }
            if (lane < 4){
                int c = wn*40 + nt*8 + lane*2;
                colp[j*320 + wm*80 + c]     = c0m;
                colp[j*320 + wm*80 + c + 1] = c1m;
            }
        }
    }
    __syncthreads();

    #pragma unroll
    for (int j = 0; j < 2; j++){
        const int len = j ? len1 : len0;
        float contrib = 0.f;
        if (tid < vlim){
            float r = fmaxf(rowp[j*256 + tid], rowp[j*256 + 128 + tid]);
            if (len < NT) r = fmaxf(r, 0.f);
            contrib = r;
        }
        #pragma unroll
        for (int o = 16; o > 0; o >>= 1) contrib += __shfl_xor_sync(0xffffffffu, contrib, o);
        if (lane == 0) red[j*8 + warp] = contrib;
    }
    __syncthreads();
    if (warp < 2){
        float s = (lane < 8) ? red[warp*8 + lane] : 0.f;
        #pragma unroll
        for (int o = 4; o > 0; o >>= 1) s += __shfl_xor_sync(0xffffffffu, s, o);
        if (lane == 0) g_rs[Z][b*NQ + q0 + warp] = s;
    }
    if (tid < 160){
        int j = tid / 80, t = tid - j*80;
        float cm = fmaxf(fmaxf(colp[j*320 + t],       colp[j*320 + 80 + t]),
                         fmaxf(colp[j*320 + 160 + t], colp[j*320 + 240 + t]));
        g_cm[Z][(size_t)(b*NQ + q0 + j)*80 + t] = cm;
    }
}

// ---------------------------------------------------------------------------
// K5: finish — combine the two M-halves. One warp per (b,q).
// ---------------------------------------------------------------------------
__global__ __launch_bounds__(256) void finish_kernel(
    const int* __restrict__ text_length, float* __restrict__ out)
{
    const int gw = blockIdx.x*8 + (threadIdx.x >> 5);
    const int lane = threadIdx.x & 31;
    if (gw >= NB*NQ) return;
    const int q = gw % NQ, b = gw / NQ;
    const int len = text_length[q];
    float ts = 0.f;
    for (int t = lane; t < len; t += 32)
        ts += fmaxf(g_cm[0][(size_t)gw*80 + t], g_cm[1][(size_t)gw*80 + t]);
    #pragma unroll
    for (int o = 16; o > 0; o >>= 1) ts += __shfl_xor_sync(0xffffffffu, ts, o);
    if (lane == 0){
        out[2*NB*NE         + (size_t)b*NQ + q] = ts / (float)len;
        out[2*NB*NE + NB*NQ + (size_t)b*NQ + q] = (g_rs[0][gw] + g_rs[1][gw]) / (float)NV;
    }
}

extern "C" void kernel_launch(void* const* d_in, const int* in_sizes, int n_in,
                              void* d_out, int out_size) {
    const float* visual_cls    = (const float*)d_in[0];
    const float* visual_tokens = (const float*)d_in[1];
    const float* textual_cls   = (const float*)d_in[2];
    const float* textual_tokens= (const float*)d_in[3];
    const float* Wv_cls = (const float*)d_in[4];
    const float* bv_cls = (const float*)d_in[5];
    const float* Wt_cls = (const float*)d_in[6];
    const float* bt_cls = (const float*)d_in[7];
    const float* Wv_tok = (const float*)d_in[8];
    const float* bv_tok = (const float*)d_in[9];
    const float* Wt_tok = (const float*)d_in[10];
    const float* bt_tok = (const float*)d_in[11];
    const int*   text_length = (const int*)d_in[12];
    float* out = (float*)d_out;

    static bool attr_done = false;
    if (!attr_done){
        cudaFuncSetAttribute(fg10_kernel<0>, cudaFuncAttributeMaxDynamicSharedMemorySize, FG10_SMEM);
        cudaFuncSetAttribute(fg10_kernel<1>, cudaFuncAttributeMaxDynamicSharedMemorySize, FG10_SMEM);
        cudaFuncSetAttribute(tok_gemm4,      cudaFuncAttributeMaxDynamicSharedMemorySize, TOK_SMEM);
        attr_done = true;
    }

    {
        const int total = (RV + RT + 2*NE) * (ND/4);
        cvt_kernel<<<(total + 255)/256, 256>>>(visual_tokens, textual_tokens,
                                               Wv_tok, Wt_tok);
    }
    tok_gemm4<<<dim3(TOK_VBLK + (RT+127)/128, 4), 256, TOK_SMEM>>>(bv_tok, bt_tok);
    norm_kernel3<<<(RV + RT)/8, 256>>>();
    fg10_kernel<0><<<dim3(NQ/2, NB), 256, FG10_SMEM>>>(text_length);
    fg10_kernel<1><<<dim3(NQ/2, NB), 256, FG10_SMEM>>>(text_length);
    cls_gemm<<<dim3(6,8,2), 256>>>(visual_cls, textual_cls,
                                   Wv_cls, bv_cls, Wt_cls, bt_cls, out);
    finish_kernel<<<(NB*NQ + 7)/8, 256>>>(text_length, out);
}